// round 1
// baseline (speedup 1.0000x reference)
#include <cuda_runtime.h>
#include <math.h>

#define BSZ   8
#define N0    4096
#define NMSG  4
#define NTOT  4100
#define CDIM  128
#define DH    32
#define ATT_SCALE 0.17677669529663687f  // 1/sqrt(32)

#define L1   256
#define LT1  260
#define HR1  16
#define WR1  16
#define L2   1024
#define LT2  1028
#define HR2  32
#define WR2  32

// ---------------- scratch (static device globals; no allocs) ----------------
__device__ float g_q[BSZ * NTOT * CDIM];       // Q projection [b][n][128]
__device__ float g_xk1[BSZ * LT1 * CDIM];      // branch1 tokens (pre/post LN in place)
__device__ float g_xk2[BSZ * LT2 * CDIM];
__device__ float g_kv1[BSZ * LT1 * CDIM];      // kv: o = t*64 + hh*32 + d
__device__ float g_kv2[BSZ * LT2 * CDIM];
__device__ float g_v1m[BSZ * LT1 * 64];        // v + dwconv(v) (msg: 2v), ch = hh*32+d
__device__ float g_v2m[BSZ * LT2 * 64];
__device__ float g_x12[BSZ * NTOT * CDIM];     // attention outputs, col = hg*32+d

enum { MODE_Q = 0, MODE_PATCH = 1, MODE_PLAIN = 2, MODE_PROJ = 3 };

// ---------------------------------------------------------------------------
// Generic tiled GEMM: Y[M,128] = X[M,K] @ W[128,K]^T + bias, with mode-specific
// X gather and epilogue. Block = 32 rows x 128 cols, BK=32, 256 threads,
// 4x4 register micro-tile per thread.
// ---------------------------------------------------------------------------
template <int MODE, int S>
__global__ void gemm128_kernel(const float* __restrict__ Acont,
                               const float* __restrict__ xsrc,
                               const float* __restrict__ msgsrc,
                               const float* __restrict__ Wt,
                               const float* __restrict__ bias,
                               float* __restrict__ out,
                               float* __restrict__ out2,
                               int M, int K, int Wr, int L, int Lt) {
    __shared__ float Xs[32][33];
    __shared__ float Ws[32][132];  // Ws[kk][col]

    const int tid  = threadIdx.x;
    const int trow = tid >> 5;   // 0..7  -> 4 rows each
    const int tcol = tid & 31;   // 0..31 -> 4 cols each
    const int rowBase = blockIdx.x * 32;

    float acc[4][4];
#pragma unroll
    for (int i = 0; i < 4; i++)
#pragma unroll
        for (int j = 0; j < 4; j++) acc[i][j] = 0.f;

    for (int k0 = 0; k0 < K; k0 += 32) {
        // load W chunk: coalesced along k
#pragma unroll
        for (int i = 0; i < 16; i++) {
            int idx = tid + i * 256;        // 0..4095
            int col = idx >> 5;
            int kk  = idx & 31;
            Ws[kk][col] = Wt[col * K + k0 + kk];
        }
        // load X chunk
#pragma unroll
        for (int i = 0; i < 4; i++) {
            int idx = tid + i * 256;        // 0..1023
            int r  = idx >> 5;
            int kk = idx & 31;
            int gr = rowBase + r;
            int k  = k0 + kk;
            float v = 0.f;
            if (gr < M) {
                if (MODE == MODE_Q) {
                    int b = gr / NTOT, n = gr - b * NTOT;
                    v = (n < N0) ? xsrc[(b * N0 + n) * CDIM + k]
                                 : msgsrc[(b * NMSG + (n - N0)) * CDIM + k];
                } else if (MODE == MODE_PATCH) {
                    const int SS = S * S;
                    int b = gr / L, l = gr - b * L;
                    int hr = l / Wr, wr = l - hr * Wr;
                    int c   = k / SS;
                    int pos = k - c * SS;
                    int ky = pos / S, kx = pos - ky * S;
                    int p = (hr * S + ky) * 64 + (wr * S + kx);
                    v = xsrc[(b * N0 + p) * CDIM + c];
                } else {  // PLAIN / PROJ: contiguous [M][128]
                    v = Acont[gr * CDIM + k];
                }
            }
            Xs[r][kk] = v;
        }
        __syncthreads();
#pragma unroll
        for (int kk = 0; kk < 32; kk++) {
            float a0 = Xs[trow * 4 + 0][kk];
            float a1 = Xs[trow * 4 + 1][kk];
            float a2 = Xs[trow * 4 + 2][kk];
            float a3 = Xs[trow * 4 + 3][kk];
            float b0 = Ws[kk][tcol * 4 + 0];
            float b1 = Ws[kk][tcol * 4 + 1];
            float b2 = Ws[kk][tcol * 4 + 2];
            float b3 = Ws[kk][tcol * 4 + 3];
            acc[0][0] += a0 * b0; acc[0][1] += a0 * b1; acc[0][2] += a0 * b2; acc[0][3] += a0 * b3;
            acc[1][0] += a1 * b0; acc[1][1] += a1 * b1; acc[1][2] += a1 * b2; acc[1][3] += a1 * b3;
            acc[2][0] += a2 * b0; acc[2][1] += a2 * b1; acc[2][2] += a2 * b2; acc[2][3] += a2 * b3;
            acc[3][0] += a3 * b0; acc[3][1] += a3 * b1; acc[3][2] += a3 * b2; acc[3][3] += a3 * b3;
        }
        __syncthreads();
    }

#pragma unroll
    for (int i = 0; i < 4; i++) {
        int gr = rowBase + trow * 4 + i;
        if (gr >= M) continue;
#pragma unroll
        for (int j = 0; j < 4; j++) {
            int col = tcol * 4 + j;
            float v = acc[i][j] + bias[col];
            if (MODE == MODE_PROJ) {
                int b = gr / NTOT, n = gr - b * NTOT;
                if (n < N0) {
                    v += xsrc[(b * N0 + n) * CDIM + col];
                    out[(b * N0 + n) * CDIM + col] = v;
                } else {
                    v += msgsrc[(b * NMSG + (n - N0)) * CDIM + col];
                    out2[(b * NMSG + (n - N0)) * CDIM + col] = v;
                }
            } else if (MODE == MODE_PATCH) {
                int b = gr / L, l = gr - b * L;
                out[(b * Lt + l) * CDIM + col] = v;
            } else {
                out[gr * CDIM + col] = v;
            }
        }
    }
}

// ---------------------------------------------------------------------------
// msg tokens through SR conv via summed weights: xk[b, L+n, o] = msg.Wsum^T + b
// ---------------------------------------------------------------------------
__global__ void msgr_kernel(const float* __restrict__ msg,
                            const float* __restrict__ srw,
                            const float* __restrict__ srb,
                            float* __restrict__ xk, int SS, int L, int Lt) {
    int o = threadIdx.x;  // 128
    int r = blockIdx.x;   // B*NMSG
    int b = r / NMSG, n = r - b * NMSG;
    float acc = srb[o];
    for (int c = 0; c < CDIM; c++) {
        const float* wp = srw + (o * CDIM + c) * SS;
        float ws = 0.f;
        for (int p = 0; p < SS; p++) ws += wp[p];
        acc += msg[(b * NMSG + n) * CDIM + c] * ws;
    }
    xk[(b * Lt + L + n) * CDIM + o] = acc;
}

// ---------------------------------------------------------------------------
// LayerNorm + exact GELU, in place. One block (128 threads) per row.
// ---------------------------------------------------------------------------
__global__ void ln_gelu_kernel(float* __restrict__ buf,
                               const float* __restrict__ g,
                               const float* __restrict__ be) {
    __shared__ float red[128];
    int r = blockIdx.x;
    int t = threadIdx.x;
    float v = buf[r * CDIM + t];
    red[t] = v;
    __syncthreads();
    for (int o = 64; o > 0; o >>= 1) {
        if (t < o) red[t] += red[t + o];
        __syncthreads();
    }
    float mu = red[0] * (1.f / 128.f);
    __syncthreads();
    float d = v - mu;
    red[t] = d * d;
    __syncthreads();
    for (int o = 64; o > 0; o >>= 1) {
        if (t < o) red[t] += red[t + o];
        __syncthreads();
    }
    float var = red[0] * (1.f / 128.f);
    float y = d * rsqrtf(var + 1e-5f) * g[t] + be[t];
    float gel = 0.5f * y * (1.f + erff(y * 0.70710678118654752f));
    buf[r * CDIM + t] = gel;
}

// ---------------------------------------------------------------------------
// v_mod: spatial tokens get v + depthwise3x3(v) + bias; msg tokens get 2v.
// ---------------------------------------------------------------------------
__global__ void vmod_kernel(const float* __restrict__ kv,
                            const float* __restrict__ lw,
                            const float* __restrict__ lb,
                            float* __restrict__ vm,
                            int Hr, int Wr, int L, int Lt) {
    int ch = threadIdx.x;  // 0..63
    int r  = blockIdx.x;   // B*Lt
    int b = r / Lt, l = r - b * Lt;
    float self = kv[(b * Lt + l) * CDIM + 64 + ch];
    float o;
    if (l < L) {
        int hr = l / Wr, wr = l - hr * Wr;
        float acc = lb[ch];
#pragma unroll
        for (int dy = 0; dy < 3; dy++) {
#pragma unroll
            for (int dx = 0; dx < 3; dx++) {
                int yy = hr + dy - 1, xx = wr + dx - 1;
                if (yy >= 0 && yy < Hr && xx >= 0 && xx < Wr)
                    acc += lw[ch * 9 + dy * 3 + dx] *
                           kv[(b * Lt + yy * Wr + xx) * CDIM + 64 + ch];
            }
        }
        o = self + acc;
    } else {
        o = 2.f * self;
    }
    vm[(b * Lt + l) * 64 + ch] = o;
}

// ---------------------------------------------------------------------------
// Flash-style attention. Block = (qtile of 64, head hh in {0,1}, batch b).
// 8 warps, each owns 8 query rows; K/V streamed in 64-key chunks.
// ---------------------------------------------------------------------------
__global__ void attn_kernel(const float* __restrict__ q,
                            const float* __restrict__ kv,
                            const float* __restrict__ vm,
                            float* __restrict__ out,
                            int Lt, int hgBase) {
    __shared__ float Qs[64][36];
    __shared__ float Ks[64][36];
    __shared__ float Vs[64][36];
    __shared__ float Ps[8][8][64];

    const int tid  = threadIdx.x;
    const int warp = tid >> 5;
    const int lane = tid & 31;
    const int qt = blockIdx.x, hh = blockIdx.y, b = blockIdx.z;
    const int hg = hgBase + hh;
    const int n0 = qt * 64;

    // load Q tile
#pragma unroll
    for (int i = 0; i < 8; i++) {
        int idx = tid + i * 256;
        int r = idx >> 5, d = idx & 31;
        int n = n0 + r;
        Qs[r][d] = (n < NTOT) ? q[(b * NTOT + n) * CDIM + hg * DH + d] : 0.f;
    }
    __syncthreads();

    float m_i[8], l_i[8], o_i[8];
#pragma unroll
    for (int i = 0; i < 8; i++) { m_i[i] = -1e30f; l_i[i] = 0.f; o_i[i] = 0.f; }

    const int nc = (Lt + 63) >> 6;
    for (int ci = 0; ci < nc; ci++) {
        int c0 = ci << 6;
#pragma unroll
        for (int i = 0; i < 8; i++) {
            int idx = tid + i * 256;
            int r = idx >> 5, d = idx & 31;
            int gl = c0 + r;
            float kk = 0.f, vv = 0.f;
            if (gl < Lt) {
                kk = kv[(b * Lt + gl) * CDIM + hh * DH + d];
                vv = vm[(b * Lt + gl) * 64 + hh * DH + d];
            }
            Ks[r][d] = kk;
            Vs[r][d] = vv;
        }
        __syncthreads();

        // scores: each lane handles columns lane and lane+32
        float s0[8], s1[8];
#pragma unroll
        for (int i = 0; i < 8; i++) { s0[i] = 0.f; s1[i] = 0.f; }
#pragma unroll
        for (int k4 = 0; k4 < 8; k4++) {
            float4 ka = *(const float4*)&Ks[lane][k4 * 4];
            float4 kb = *(const float4*)&Ks[lane + 32][k4 * 4];
#pragma unroll
            for (int i = 0; i < 8; i++) {
                float4 qv = *(const float4*)&Qs[warp * 8 + i][k4 * 4];
                s0[i] += qv.x * ka.x + qv.y * ka.y + qv.z * ka.z + qv.w * ka.w;
                s1[i] += qv.x * kb.x + qv.y * kb.y + qv.z * kb.z + qv.w * kb.w;
            }
        }
        bool v0 = (c0 + lane) < Lt;
        bool v1 = (c0 + lane + 32) < Lt;
#pragma unroll
        for (int i = 0; i < 8; i++) {
            float a = v0 ? s0[i] * ATT_SCALE : -1e30f;
            float c = v1 ? s1[i] * ATT_SCALE : -1e30f;
            float mx = fmaxf(a, c);
#pragma unroll
            for (int off = 16; off > 0; off >>= 1)
                mx = fmaxf(mx, __shfl_xor_sync(0xffffffffu, mx, off));
            float mnew = fmaxf(m_i[i], mx);
            float corr = __expf(m_i[i] - mnew);
            float p0 = __expf(a - mnew);
            float p1 = __expf(c - mnew);
            float ps = p0 + p1;
#pragma unroll
            for (int off = 16; off > 0; off >>= 1)
                ps += __shfl_xor_sync(0xffffffffu, ps, off);
            l_i[i] = l_i[i] * corr + ps;
            o_i[i] *= corr;
            m_i[i] = mnew;
            Ps[warp][i][lane] = p0;
            Ps[warp][i][lane + 32] = p1;
        }
        __syncwarp();

        // AV: o_i[i][lane] += sum_l P[i][l] * V[l][lane]
#pragma unroll
        for (int l4 = 0; l4 < 16; l4++) {
            float va = Vs[l4 * 4 + 0][lane];
            float vb = Vs[l4 * 4 + 1][lane];
            float vc = Vs[l4 * 4 + 2][lane];
            float vd = Vs[l4 * 4 + 3][lane];
#pragma unroll
            for (int i = 0; i < 8; i++) {
                float4 p = *(const float4*)&Ps[warp][i][l4 * 4];
                o_i[i] += p.x * va + p.y * vb + p.z * vc + p.w * vd;
            }
        }
        __syncthreads();
    }

#pragma unroll
    for (int i = 0; i < 8; i++) {
        int n = n0 + warp * 8 + i;
        if (n < NTOT)
            out[(b * NTOT + n) * CDIM + hg * DH + lane] = o_i[i] / l_i[i];
    }
}

// ---------------------------------------------------------------------------
extern "C" void kernel_launch(void* const* d_in, const int* in_sizes, int n_in,
                              void* d_out, int out_size) {
    const float* x     = (const float*)d_in[0];
    const float* msg   = (const float*)d_in[1];
    const float* Wq    = (const float*)d_in[2];
    const float* bq    = (const float*)d_in[3];
    const float* sr1w  = (const float*)d_in[4];
    const float* sr1b  = (const float*)d_in[5];
    const float* ln1g  = (const float*)d_in[6];
    const float* ln1b  = (const float*)d_in[7];
    const float* sr2w  = (const float*)d_in[8];
    const float* sr2b  = (const float*)d_in[9];
    const float* ln2g  = (const float*)d_in[10];
    const float* ln2b  = (const float*)d_in[11];
    const float* kv1w  = (const float*)d_in[12];
    const float* kv1b  = (const float*)d_in[13];
    const float* kv2w  = (const float*)d_in[14];
    const float* kv2b  = (const float*)d_in[15];
    const float* lc1w  = (const float*)d_in[16];
    const float* lc1b  = (const float*)d_in[17];
    const float* lc2w  = (const float*)d_in[18];
    const float* lc2b  = (const float*)d_in[19];
    const float* projw = (const float*)d_in[20];
    const float* projb = (const float*)d_in[21];
    (void)in_sizes; (void)n_in; (void)out_size;

    float* out_img = (float*)d_out;
    float* out_msg = out_img + (size_t)BSZ * N0 * CDIM;

    float *q, *xk1, *xk2, *kv1, *kv2, *v1m, *v2m, *x12;
    cudaGetSymbolAddress((void**)&q,   g_q);
    cudaGetSymbolAddress((void**)&xk1, g_xk1);
    cudaGetSymbolAddress((void**)&xk2, g_xk2);
    cudaGetSymbolAddress((void**)&kv1, g_kv1);
    cudaGetSymbolAddress((void**)&kv2, g_kv2);
    cudaGetSymbolAddress((void**)&v1m, g_v1m);
    cudaGetSymbolAddress((void**)&v2m, g_v2m);
    cudaGetSymbolAddress((void**)&x12, g_x12);

    // 1. Q projection: [B*4100,128] = concat(x,msg) @ Wq^T + bq
    gemm128_kernel<MODE_Q, 1><<<(BSZ * NTOT + 31) / 32, 256>>>(
        nullptr, x, msg, Wq, bq, q, nullptr, BSZ * NTOT, CDIM, 0, 0, 0);

    // 2. SR patch-embed convs (im2col GEMMs)
    gemm128_kernel<MODE_PATCH, 4><<<(BSZ * L1 + 31) / 32, 256>>>(
        nullptr, x, nullptr, sr1w, sr1b, xk1, nullptr, BSZ * L1, CDIM * 16, WR1, L1, LT1);
    gemm128_kernel<MODE_PATCH, 2><<<(BSZ * L2 + 31) / 32, 256>>>(
        nullptr, x, nullptr, sr2w, sr2b, xk2, nullptr, BSZ * L2, CDIM * 4, WR2, L2, LT2);

    // 3. msg tokens through summed SR weights
    msgr_kernel<<<BSZ * NMSG, 128>>>(msg, sr1w, sr1b, xk1, 16, L1, LT1);
    msgr_kernel<<<BSZ * NMSG, 128>>>(msg, sr2w, sr2b, xk2, 4, L2, LT2);

    // 4. LayerNorm + GELU (in place)
    ln_gelu_kernel<<<BSZ * LT1, 128>>>(xk1, ln1g, ln1b);
    ln_gelu_kernel<<<BSZ * LT2, 128>>>(xk2, ln2g, ln2b);

    // 5. KV projections
    gemm128_kernel<MODE_PLAIN, 1><<<(BSZ * LT1 + 31) / 32, 256>>>(
        xk1, nullptr, nullptr, kv1w, kv1b, kv1, nullptr, BSZ * LT1, CDIM, 0, 0, 0);
    gemm128_kernel<MODE_PLAIN, 1><<<(BSZ * LT2 + 31) / 32, 256>>>(
        xk2, nullptr, nullptr, kv2w, kv2b, kv2, nullptr, BSZ * LT2, CDIM, 0, 0, 0);

    // 6. V augmentation (depthwise conv / 2x for msg)
    vmod_kernel<<<BSZ * LT1, 64>>>(kv1, lc1w, lc1b, v1m, HR1, WR1, L1, LT1);
    vmod_kernel<<<BSZ * LT2, 64>>>(kv2, lc2w, lc2b, v2m, HR2, WR2, L2, LT2);

    // 7. attention, both branches, writing into g_x12 (col = hg*32 + d)
    {
        dim3 grid1((NTOT + 63) / 64, 2, BSZ);
        attn_kernel<<<grid1, 256>>>(q, kv1, v1m, x12, LT1, 0);
        dim3 grid2((NTOT + 63) / 64, 2, BSZ);
        attn_kernel<<<grid2, 256>>>(q, kv2, v2m, x12, LT2, 2);
    }

    // 8. output projection + residual, split write to d_out
    gemm128_kernel<MODE_PROJ, 1><<<(BSZ * NTOT + 31) / 32, 256>>>(
        x12, x, msg, projw, projb, out_img, out_msg, BSZ * NTOT, CDIM, 0, 0, 0);
}